// round 7
// baseline (speedup 1.0000x reference)
#include <cuda_runtime.h>
#include <cuda_bf16.h>

// NLL sequence loss: only the last valid timestep per batch row contributes.
//   loss = -(1/B) * sum_b inputs[b, min(T,length[b])-1, target[b]]
//
// CONVERGED FINAL FORM (measured fastest: 6.624us; bench floor is ~6.6us of
// graph-replay/launch overhead, kernel body ~0.3us warm).
//
// 4 warps x 4 rows/thread:
//  - length/target read as one int4 per array per thread (one memory round).
//  - 4 independent gathers per thread; all 512 gathers overlap in a single
//    L2/DRAM latency round chip-wide (gather = irreducible dependent
//    two-load chain).
//  - Reduction: 3 register adds -> 5 warp shuffles -> 4 smem words -> one
//    thread does 3 adds + negate-scale FMUL + store.

#define B_DIM 512
#define T_DIM 128
#define C_DIM 2000
#define NTHREADS 128
#define RPT 4   // rows per thread = B_DIM / NTHREADS
#define NWARPS (NTHREADS / 32)

__global__ __launch_bounds__(NTHREADS, 1)
void nll_seq_loss_kernel(const float* __restrict__ inputs,
                         const int*   __restrict__ length,
                         const int*   __restrict__ target,
                         float*       __restrict__ out) {
    const int t = threadIdx.x;
    const int base = t * RPT;   // contiguous 4-row chunk -> aligned int4

    int4 l = *(const int4*)(length + base);
    int4 g = *(const int4*)(target + base);

    int len[RPT] = {l.x, l.y, l.z, l.w};
    int tgt[RPT] = {g.x, g.y, g.z, g.w};

    float v[RPT];
    #pragma unroll
    for (int j = 0; j < RPT; j++) {
        int last = (len[j] < T_DIM ? len[j] : T_DIM) - 1;
        int idx = ((base + j) * T_DIM + last) * C_DIM + tgt[j];
        v[j] = __ldg(inputs + idx);
    }

    float s = (v[0] + v[1]) + (v[2] + v[3]);

    #pragma unroll
    for (int off = 16; off > 0; off >>= 1)
        s += __shfl_down_sync(0xFFFFFFFFu, s, off);

    __shared__ float warp_sums[NWARPS];
    const int lane = t & 31;
    const int wid  = t >> 5;
    if (lane == 0) warp_sums[wid] = s;
    __syncthreads();

    if (t == 0) {
        float w = (warp_sums[0] + warp_sums[1]) + (warp_sums[2] + warp_sums[3]);
        out[0] = w * (-1.0f / (float)B_DIM);
    }
}

extern "C" void kernel_launch(void* const* d_in, const int* in_sizes, int n_in,
                              void* d_out, int out_size) {
    const float* inputs = (const float*)d_in[0];
    const int*   length = (const int*)d_in[1];
    const int*   target = (const int*)d_in[2];
    float*       out    = (float*)d_out;

    nll_seq_loss_kernel<<<1, NTHREADS>>>(inputs, length, target, out);
}

// round 8
// speedup vs baseline: 1.0914x; 1.0914x over previous
#include <cuda_runtime.h>
#include <cuda_bf16.h>

// NLL sequence loss: only the last valid timestep per batch row contributes.
//   loss = -(1/B) * sum_b inputs[b, min(T,length[b])-1, target[b]]
//
// CONVERGED FINAL FORM. Best measured 6.624us; identical binary re-measured
// at 6.880us (R7), establishing bench noise of +/-0.25us on a ~6.6us
// graph-replay/launch floor. Warm kernel body is ~0.3us: one vectorized
// index-load round -> one fully-overlapped dependent gather round (512
// scattered 4B loads, irreducible for data-dependent addressing) -> ~150cyc
// reduction tail. All ncu pipes <=0.2%; no hardware roofline applies to 2KB
// of useful traffic.
//
// 4 warps x 4 rows/thread:
//  - length/target read as one int4 per array per thread.
//  - 4 independent gathers per thread; all 512 gathers overlap in a single
//    L2/DRAM latency round chip-wide.
//  - Reduction: 3 register adds -> 5 warp shuffles -> 4 smem words -> one
//    thread does 3 adds + negate-scale multiply + store.

#define B_DIM 512
#define T_DIM 128
#define C_DIM 2000
#define NTHREADS 128
#define RPT 4   // rows per thread = B_DIM / NTHREADS
#define NWARPS (NTHREADS / 32)

__global__ __launch_bounds__(NTHREADS, 1)
void nll_seq_loss_kernel(const float* __restrict__ inputs,
                         const int*   __restrict__ length,
                         const int*   __restrict__ target,
                         float*       __restrict__ out) {
    const int t = threadIdx.x;
    const int base = t * RPT;   // contiguous 4-row chunk -> aligned int4

    int4 l = *(const int4*)(length + base);
    int4 g = *(const int4*)(target + base);

    int len[RPT] = {l.x, l.y, l.z, l.w};
    int tgt[RPT] = {g.x, g.y, g.z, g.w};

    float v[RPT];
    #pragma unroll
    for (int j = 0; j < RPT; j++) {
        int last = (len[j] < T_DIM ? len[j] : T_DIM) - 1;
        int idx = ((base + j) * T_DIM + last) * C_DIM + tgt[j];
        v[j] = __ldg(inputs + idx);
    }

    float s = (v[0] + v[1]) + (v[2] + v[3]);

    #pragma unroll
    for (int off = 16; off > 0; off >>= 1)
        s += __shfl_down_sync(0xFFFFFFFFu, s, off);

    __shared__ float warp_sums[NWARPS];
    const int lane = t & 31;
    const int wid  = t >> 5;
    if (lane == 0) warp_sums[wid] = s;
    __syncthreads();

    if (t == 0) {
        float w = (warp_sums[0] + warp_sums[1]) + (warp_sums[2] + warp_sums[3]);
        out[0] = w * (-1.0f / (float)B_DIM);
    }
}

extern "C" void kernel_launch(void* const* d_in, const int* in_sizes, int n_in,
                              void* d_out, int out_size) {
    const float* inputs = (const float*)d_in[0];
    const int*   length = (const int*)d_in[1];
    const int*   target = (const int*)d_in[2];
    float*       out    = (float*)d_out;

    nll_seq_loss_kernel<<<1, NTHREADS>>>(inputs, length, target, out);
}